// round 4
// baseline (speedup 1.0000x reference)
#include <cuda_runtime.h>
#include <cuda_bf16.h>

// TextureMartingaleModule: per-channel 3x3 GLCM-style features, zero padding.
// x: [B=8, C=16, H=256, W=256] f32 -> out: [B, C*4, H, W] f32
// Per window (K=9): mean, std(ddof=1)+eps
//   contrast    = mean(((p-mean)/std)^2)
//   energy      = mean(p^2)
//   entropy     = -mean(p*log(p+eps))
//   homogeneity = 1 / mean(1 + |p-mean|)
// M = exp(theta*log(f+eps) - 0.5*theta^2), theta=1  ==  (f+eps)*exp(-0.5)

#define HH 256
#define WW 256
#define TILE 32
#define SROW 34
#define EPSF 1e-6f
#define EXPN 0.60653065971263342f  /* e^-0.5 */

__global__ __launch_bounds__(256, 6)
void glcm_martingale_kernel(const float* __restrict__ x, float* __restrict__ out)
{
    __shared__ float sp[SROW * SROW];   // raw values (zero-padded halo)
    __shared__ float sl[SROW * SROW];   // p * log(p + eps), precomputed once per element

    const int bc    = blockIdx.z;                 // b*C + c  (128 planes)
    const int tileX = blockIdx.x * TILE;
    const int tileY = blockIdx.y * TILE;
    const float* __restrict__ xin = x + (size_t)bc * (HH * WW);

    const int tid = threadIdx.y * 32 + threadIdx.x;

    // ---- load 34x34 halo tile; compute plog once per element ----
    #pragma unroll
    for (int i = tid; i < SROW * SROW; i += 256) {
        int r  = i / SROW;
        int cc = i - r * SROW;
        int gh = tileY - 1 + r;
        int gw = tileX - 1 + cc;
        float v = 0.0f;
        if ((unsigned)gh < (unsigned)HH && (unsigned)gw < (unsigned)WW)
            v = xin[gh * WW + gw];
        sp[i] = v;
        sl[i] = v * __logf(v + EPSF);   // v=0 -> 0 * log(eps) = 0, matches pad
    }
    __syncthreads();

    const int tx = threadIdx.x;         // output col within tile (0..31)
    const int ty = threadIdx.y;         // row group (0..7), 4 rows each
    const int r0 = ty * 4;              // first output row in tile

    // Rolling 3x3 window of p in registers + rolling row sums.
    float p0a, p0b, p0c, p1a, p1b, p1c;
    float rs0, rs1, rq0, rq1, rl0, rl1;
    {
        const float* row0 = sp + r0 * SROW + tx;
        const float* row1 = sp + (r0 + 1) * SROW + tx;
        p0a = row0[0]; p0b = row0[1]; p0c = row0[2];
        p1a = row1[0]; p1b = row1[1]; p1c = row1[2];
        const float* l0 = sl + r0 * SROW + tx;
        const float* l1 = sl + (r0 + 1) * SROW + tx;
        rl0 = l0[0] + l0[1] + l0[2];
        rl1 = l1[0] + l1[1] + l1[2];
        rs0 = p0a + p0b + p0c;
        rq0 = fmaf(p0a, p0a, fmaf(p0b, p0b, p0c * p0c));
        rs1 = p1a + p1b + p1c;
        rq1 = fmaf(p1a, p1a, fmaf(p1b, p1b, p1c * p1c));
    }

    const size_t plane = (size_t)HH * WW;
    float* obase = out + (size_t)bc * 4 * plane
                       + (size_t)(tileY + r0) * WW + (tileX + tx);

    #pragma unroll
    for (int k = 0; k < 4; k++) {
        const int s = r0 + k + 2;
        const float* row = sp + s * SROW + tx;
        float p2a = row[0], p2b = row[1], p2c = row[2];
        const float* lrow = sl + s * SROW + tx;
        float rl2 = lrow[0] + lrow[1] + lrow[2];
        float rs2 = p2a + p2b + p2c;
        float rq2 = fmaf(p2a, p2a, fmaf(p2b, p2b, p2c * p2c));

        float S1 = rs0 + rs1 + rs2;     // sum p
        float S2 = rq0 + rq1 + rq2;     // sum p^2
        float SL = rl0 + rl1 + rl2;     // sum p*log(p+eps)

        float mean = S1 * (1.0f / 9.0f);

        // deviation pass: sum |dev| (homogeneity) and sum dev^2 (std/contrast)
        float a = 0.0f, sd = 0.0f, d;
        d = p0a - mean; a += fabsf(d); sd = fmaf(d, d, sd);
        d = p0b - mean; a += fabsf(d); sd = fmaf(d, d, sd);
        d = p0c - mean; a += fabsf(d); sd = fmaf(d, d, sd);
        d = p1a - mean; a += fabsf(d); sd = fmaf(d, d, sd);
        d = p1b - mean; a += fabsf(d); sd = fmaf(d, d, sd);
        d = p1c - mean; a += fabsf(d); sd = fmaf(d, d, sd);
        d = p2a - mean; a += fabsf(d); sd = fmaf(d, d, sd);
        d = p2b - mean; a += fabsf(d); sd = fmaf(d, d, sd);
        d = p2c - mean; a += fabsf(d); sd = fmaf(d, d, sd);

        // std = sqrt(sd/8) + eps ; contrast = (sd/9) / std^2
        // 1/(sqrt(v)+eps) ~= rsq*(1 - eps*rsq), valid since std >> eps here
        float v   = sd * 0.125f;
        float rsq = rsqrtf(v);
        float inv = rsq * fmaf(-EPSF, rsq, 1.0f);
        float contrast = sd * (1.0f / 9.0f) * inv * inv;

        float energy  = S2 * (1.0f / 9.0f);
        float entropy = -SL * (1.0f / 9.0f);
        float m       = fmaf(a, 1.0f / 9.0f, 1.0f);   // mean(1+|dev|)
        float homog   = __fdividef(1.0f, m);

        // M = (f + eps) * e^{-0.5}
        float* o = obase + (size_t)k * WW;
        o[0]         = fmaf(contrast, EXPN, EPSF * EXPN);
        o[plane]     = fmaf(energy,   EXPN, EPSF * EXPN);
        o[2 * plane] = fmaf(entropy,  EXPN, EPSF * EXPN);
        o[3 * plane] = fmaf(homog,    EXPN, EPSF * EXPN);

        // roll window down one row
        p0a = p1a; p0b = p1b; p0c = p1c;
        p1a = p2a; p1b = p2b; p1c = p2c;
        rs0 = rs1; rs1 = rs2;
        rq0 = rq1; rq1 = rq2;
        rl0 = rl1; rl1 = rl2;
    }
}

extern "C" void kernel_launch(void* const* d_in, const int* in_sizes, int n_in,
                              void* d_out, int out_size)
{
    const float* x = (const float*)d_in[0];
    float* out     = (float*)d_out;

    dim3 block(32, 8, 1);                       // 256 threads
    dim3 grid(WW / TILE, HH / TILE, 8 * 16);    // 8 x 8 x 128 = 8192 blocks
    glcm_martingale_kernel<<<grid, block>>>(x, out);
}